// round 11
// baseline (speedup 1.0000x reference)
#include <cuda_runtime.h>
#include <cstdint>

constexpr int B = 2, H = 16, L = 2048, D = 64;
constexpr int BQ = 64, BK = 64;
constexpr int PW = 68;                // smem row stride (floats); 68 mod 32 = 4 -> LDSM conflict-free
constexpr int THREADS = 128;
constexpr int NQT = L / BQ;           // 32

// scratch (pre-converted tf32, plain layouts — ldmatrix does the fragment gather)
__device__ float g_Kc[B * H * L * D];   // [bh][key][d]
__device__ float g_Vt[B * H * D * L];   // [bh][d][key]
__device__ float g_vmean[B * H * D];

__device__ __forceinline__ uint32_t tf32r(float f) {
    uint32_t u; asm("cvt.rna.tf32.f32 %0, %1;" : "=r"(u) : "f"(f)); return u;
}
__device__ __forceinline__ float tf32f(float f) { return __uint_as_float(tf32r(f)); }

__device__ __forceinline__ void mma8(float* c, uint32_t a0, uint32_t a1, uint32_t a2, uint32_t a3,
                                     uint32_t b0, uint32_t b1) {
    asm volatile(
        "mma.sync.aligned.m16n8k8.row.col.f32.tf32.tf32.f32 "
        "{%0,%1,%2,%3},{%4,%5,%6,%7},{%8,%9},{%0,%1,%2,%3};"
        : "+f"(c[0]), "+f"(c[1]), "+f"(c[2]), "+f"(c[3])
        : "r"(a0), "r"(a1), "r"(a2), "r"(a3), "r"(b0), "r"(b1));
}

// ldmatrix x4: 4 8x8-b16 matrices == 4 8x4-f32 tiles; thread(g,tig) <- f32 (row g, col tig)
__device__ __forceinline__ void ldsm4(uint32_t& r0, uint32_t& r1, uint32_t& r2, uint32_t& r3,
                                      uint32_t addr) {
    asm volatile("ldmatrix.sync.aligned.m8n8.x4.shared.b16 {%0,%1,%2,%3}, [%4];"
        : "=r"(r0), "=r"(r1), "=r"(r2), "=r"(r3) : "r"(addr));
}

__device__ __forceinline__ void cp_async16(uint32_t saddr, const void* g) {
    asm volatile("cp.async.cg.shared.global [%0], [%1], 16;" :: "r"(saddr), "l"(g));
}

// ---------------------------------------------------------------------------
// Pre-pass kernels
// ---------------------------------------------------------------------------
__global__ void kprep_kernel(const float* __restrict__ K) {
    int idx = blockIdx.x * 256 + threadIdx.x;
    g_Kc[idx] = tf32f(K[idx]);
}

__global__ void vtrans_kernel(const float* __restrict__ V) {
    __shared__ float t[64][65];
    int k0 = blockIdx.x * 64;
    int bh = blockIdx.y;
    const float* vp = V + ((size_t)bh * L + k0) * D;
    int tid = threadIdx.x;
#pragma unroll
    for (int i = 0; i < 16; ++i) {
        int e = i * 256 + tid;
        t[e >> 6][e & 63] = vp[e];
    }
    __syncthreads();
    float* op = g_Vt + (size_t)bh * D * L + k0;
#pragma unroll
    for (int i = 0; i < 16; ++i) {
        int e = i * 256 + tid;
        int d = e >> 6, c = e & 63;
        op[(size_t)d * L + c] = tf32f(t[c][d]);
    }
}

__global__ void vmean_kernel(const float* __restrict__ V) {
    int bh = blockIdx.x;
    int d = threadIdx.x & 63;
    int c = threadIdx.x >> 6;
    __shared__ float part[4][64];
    const float* vp = V + (size_t)bh * L * D;
    float s = 0.f;
    for (int k = c * 512; k < c * 512 + 512; ++k) s += vp[(size_t)k * D + d];
    part[c][d] = s;
    __syncthreads();
    if (c == 0)
        g_vmean[bh * D + d] = (part[0][d] + part[1][d] + part[2][d] + part[3][d]) * (1.0f / 2048.0f);
}

// ---------------------------------------------------------------------------
// Main attention kernel: 4 warps, Q/P in registers, B-frags via ldmatrix,
// no-max softmax, double-buffered K/V, 3 CTAs/SM
// ---------------------------------------------------------------------------
__global__ __launch_bounds__(THREADS, 3)
void attn_kernel(const float* __restrict__ Q, const int* __restrict__ qmask,
                 const int* __restrict__ vmask, const float* __restrict__ bias,
                 float* __restrict__ out) {
    extern __shared__ float smem[];

    const int qt = (NQT - 1) - blockIdx.x;        // big tiles first
    const int bh = blockIdx.y;
    const int q0 = qt * BQ;

    const float* Qg = Q + ((size_t)bh * L + q0) * D;
    const float* Kg = g_Kc + (size_t)bh * L * D;
    const float* Vg = g_Vt + (size_t)bh * D * L;
    const float* Bg = bias + ((size_t)bh * L + q0) * L;
    const int*  vmg = vmask + (size_t)bh * L;

    const int tid = threadIdx.x;
    const int w = tid >> 5, lane = tid & 31;
    const int g = lane >> 2, tig = lane & 3;

    const uint32_t sbase = (uint32_t)__cvta_generic_to_shared(smem);
    const uint32_t TSZ = BK * PW * 4;             // 17408 bytes per slot
    const uint32_t sKs[2] = { sbase, sbase + TSZ };
    const uint32_t sVs[2] = { sbase + 2 * TSZ, sbase + 3 * TSZ };

    // per-thread LDSM row address offset (bytes): lanes 0-7 row base, groups step +16B
    const uint32_t lrow = ((lane & 7) * PW + ((lane >> 3) * 4)) * 4;

    const int nkt = qt + 1;

    // prefetch tile 0: 64 rows x 16 16B-chunks each
    {
#pragma unroll
        for (int i = 0; i < 8; ++i) {
            int c = tid + i * 128;
            int r = c >> 4, sg = (c & 15) * 4;
            cp_async16(sKs[0] + (uint32_t)(r * PW + sg) * 4, Kg + r * 64 + sg);
            cp_async16(sVs[0] + (uint32_t)(r * PW + sg) * 4, Vg + (size_t)r * L + sg);
        }
        asm volatile("cp.async.commit_group;");
    }

    const int row0 = 16 * w + g;
    const int gq0 = q0 + row0, gq1 = gq0 + 8;

    // Q fragments in registers (scaled, tf32, standard m16n8k8 A layout)
    uint32_t qf[8][4];
    {
        const float* qr0 = Qg + (size_t)row0 * D;
        const float* qr1 = qr0 + 8 * D;
#pragma unroll
        for (int kk = 0; kk < 8; ++kk) {
            qf[kk][0] = tf32r(qr0[8 * kk + tig] * 0.125f);
            qf[kk][1] = tf32r(qr1[8 * kk + tig] * 0.125f);
            qf[kk][2] = tf32r(qr0[8 * kk + tig + 4] * 0.125f);
            qf[kk][3] = tf32r(qr1[8 * kk + tig + 4] * 0.125f);
        }
    }

    float o[8][4];
    float l0 = 0.f, l1 = 0.f;
#pragma unroll
    for (int j = 0; j < 8; ++j) { o[j][0] = o[j][1] = o[j][2] = o[j][3] = 0.f; }

    const int srcl = (lane & ~3) | (tig >> 1);     // P-conversion shuffle sources
    const int srcl2 = srcl + 2;
    const bool odd = tig & 1;

    for (int kt = 0; kt < nkt; ++kt) {
        const int k0 = kt * BK;
        const int buf = kt & 1;
        asm volatile("cp.async.wait_group 0;");
        __syncthreads();

        if (kt + 1 < nkt) {
            const int nk0 = (kt + 1) * BK;
            const int nb = buf ^ 1;
#pragma unroll
            for (int i = 0; i < 8; ++i) {
                int c = tid + i * 128;
                int r = c >> 4, sg = (c & 15) * 4;
                cp_async16(sKs[nb] + (uint32_t)(r * PW + sg) * 4, Kg + (size_t)(nk0 + r) * 64 + sg);
                cp_async16(sVs[nb] + (uint32_t)(r * PW + sg) * 4, Vg + (size_t)r * L + nk0 + sg);
            }
            asm volatile("cp.async.commit_group;");
        }

        // bias + mask prefetch (in flight during S-mma)
        float2 bv0[8], bv1[8];
#pragma unroll
        for (int j = 0; j < 8; ++j) {
            int c0 = k0 + 8 * j + 2 * tig;
            bv0[j] = *(const float2*)(Bg + (size_t)row0 * L + c0);
            bv1[j] = *(const float2*)(Bg + (size_t)(row0 + 8) * L + c0);
        }
        uint32_t mw0 = __ballot_sync(0xffffffffu, vmg[k0 + lane] != 0);
        uint32_t mw1 = __ballot_sync(0xffffffffu, vmg[k0 + 32 + lane] != 0);
        const int lim0 = gq0 - k0, lim1 = lim0 + 8;

        // ---- S = Q K^T  (A regs, B via LDSM) ----
        float s[8][4];
#pragma unroll
        for (int j = 0; j < 8; ++j) { s[j][0] = s[j][1] = s[j][2] = s[j][3] = 0.f; }
        const uint32_t kb = sKs[buf] + lrow;
#pragma unroll
        for (int j = 0; j < 8; ++j) {
            const uint32_t rb = kb + (uint32_t)(j * 8 * PW) * 4;
#pragma unroll
            for (int kk2 = 0; kk2 < 4; ++kk2) {
                uint32_t b0, b1, b2, b3;
                ldsm4(b0, b1, b2, b3, rb + kk2 * 64);
                mma8(s[j], qf[2 * kk2][0], qf[2 * kk2][1], qf[2 * kk2][2], qf[2 * kk2][3], b0, b1);
                mma8(s[j], qf[2 * kk2 + 1][0], qf[2 * kk2 + 1][1], qf[2 * kk2 + 1][2], qf[2 * kk2 + 1][3], b2, b3);
            }
        }

        // ---- bias + mask + exp (no-max) + C->A frag conversion via shuffles ----
        uint32_t p[8][4];
#pragma unroll
        for (int j = 0; j < 8; ++j) {
            int c0 = 8 * j + 2 * tig;
            uint32_t mw = (c0 < 32) ? mw0 : mw1;
            bool mk0 = (mw >> (c0 & 31)) & 1u;
            bool mk1 = (mw >> ((c0 + 1) & 31)) & 1u;
            float e0 = (mk0 && c0     <= lim0) ? __expf(s[j][0] + bv0[j].x) : 0.f;
            float e1 = (mk1 && c0 + 1 <= lim0) ? __expf(s[j][1] + bv0[j].y) : 0.f;
            float e2 = (mk0 && c0     <= lim1) ? __expf(s[j][2] + bv1[j].x) : 0.f;
            float e3 = (mk1 && c0 + 1 <= lim1) ? __expf(s[j][3] + bv1[j].y) : 0.f;
            l0 += e0 + e1;
            l1 += e2 + e3;
            uint32_t r0 = tf32r(e0), r1 = tf32r(e1), r2 = tf32r(e2), r3 = tf32r(e3);
            uint32_t u0 = __shfl_sync(0xffffffffu, r0, srcl);
            uint32_t u1 = __shfl_sync(0xffffffffu, r1, srcl);
            uint32_t u2 = __shfl_sync(0xffffffffu, r2, srcl);
            uint32_t u3 = __shfl_sync(0xffffffffu, r3, srcl);
            uint32_t v0 = __shfl_sync(0xffffffffu, r0, srcl2);
            uint32_t v1 = __shfl_sync(0xffffffffu, r1, srcl2);
            uint32_t v2 = __shfl_sync(0xffffffffu, r2, srcl2);
            uint32_t v3 = __shfl_sync(0xffffffffu, r3, srcl2);
            p[j][0] = odd ? u1 : u0;   // (row g,   col tig)
            p[j][1] = odd ? u3 : u2;   // (row g+8, col tig)
            p[j][2] = odd ? v1 : v0;   // (row g,   col tig+4)
            p[j][3] = odd ? v3 : v2;   // (row g+8, col tig+4)
        }

        // ---- O += P V  (A regs, B via LDSM) ----
        const uint32_t vb = sVs[buf] + lrow;
#pragma unroll
        for (int j = 0; j < 8; ++j) {
            const uint32_t rb = vb + (uint32_t)(j * 8 * PW) * 4;
#pragma unroll
            for (int kk2 = 0; kk2 < 4; ++kk2) {
                uint32_t b0, b1, b2, b3;
                ldsm4(b0, b1, b2, b3, rb + kk2 * 64);
                mma8(o[j], p[2 * kk2][0], p[2 * kk2][1], p[2 * kk2][2], p[2 * kk2][3], b0, b1);
                mma8(o[j], p[2 * kk2 + 1][0], p[2 * kk2 + 1][1], p[2 * kk2 + 1][2], p[2 * kk2 + 1][3], b2, b3);
            }
        }
    }

    // ---- epilogue: deferred l reduction over the quad ----
    l0 += __shfl_xor_sync(0xffffffffu, l0, 1);
    l0 += __shfl_xor_sync(0xffffffffu, l0, 2);
    l1 += __shfl_xor_sync(0xffffffffu, l1, 1);
    l1 += __shfl_xor_sync(0xffffffffu, l1, 2);

    int qm0 = qmask[(size_t)bh * L + gq0];
    int qm1 = qmask[(size_t)bh * L + gq1];
    bool fm0 = (l0 == 0.f), fm1 = (l1 == 0.f);
    float il0 = fm0 ? 0.f : 1.0f / l0;
    float il1 = fm1 ? 0.f : 1.0f / l1;
#pragma unroll
    for (int j = 0; j < 8; ++j) {
        int c = 8 * j + 2 * tig;
        float2 r0, r1;
        r0.x = !qm0 ? 0.f : (fm0 ? g_vmean[bh * D + c]     : o[j][0] * il0);
        r0.y = !qm0 ? 0.f : (fm0 ? g_vmean[bh * D + c + 1] : o[j][1] * il0);
        r1.x = !qm1 ? 0.f : (fm1 ? g_vmean[bh * D + c]     : o[j][2] * il1);
        r1.y = !qm1 ? 0.f : (fm1 ? g_vmean[bh * D + c + 1] : o[j][3] * il1);
        *(float2*)(out + ((size_t)bh * L + gq0) * D + c) = r0;
        *(float2*)(out + ((size_t)bh * L + gq1) * D + c) = r1;
    }
}

// ---------------------------------------------------------------------------
extern "C" void kernel_launch(void* const* d_in, const int* in_sizes, int n_in,
                              void* d_out, int out_size) {
    const float* Q  = (const float*)d_in[0];
    const float* K  = (const float*)d_in[1];
    const float* V  = (const float*)d_in[2];
    const int* qm   = (const int*)d_in[3];
    const int* vm   = (const int*)d_in[4];
    const float* bi = (const float*)d_in[5];
    float* out = (float*)d_out;

    constexpr int SMEM_BYTES = 4 * BK * PW * (int)sizeof(float);   // 69632
    cudaFuncSetAttribute(attn_kernel, cudaFuncAttributeMaxDynamicSharedMemorySize, SMEM_BYTES);

    kprep_kernel<<<(B * H * L * D) / 256, 256>>>(K);
    vtrans_kernel<<<dim3(L / 64, B * H), 256>>>(V);
    vmean_kernel<<<B * H, 256>>>(V);
    attn_kernel<<<dim3(NQT, B * H), THREADS, SMEM_BYTES>>>(Q, qm, vm, bi, out);
}

// round 13
// speedup vs baseline: 1.0541x; 1.0541x over previous
#include <cuda_runtime.h>
#include <cstdint>

constexpr int B = 2, H = 16, L = 2048, D = 64;
constexpr int BQ = 64, BK = 64;
constexpr int PW = 72;                // K/V smem row stride (floats), conflict-free LDS.64
constexpr int PB = 68;                // bias smem row stride (floats), 16B-aligned rows
constexpr int THREADS = 128;
constexpr int NQT = L / BQ;           // 32

// scratch (pre-converted tf32, mma-friendly interleaved layouts)
__device__ float g_Kc[B * H * L * D];   // [bh][key][d']   d interleaved within 8-groups
__device__ float g_Vt[B * H * D * L];   // [bh][d][key']   transposed, key interleaved
__device__ float g_vmean[B * H * D];

__device__ __forceinline__ int perm8(int k) { return 2 * (k & 3) + ((k >> 2) & 1); }
__device__ __forceinline__ int iperm8(int c) { return ((c & 1) << 2) + (c >> 1); }

__device__ __forceinline__ uint32_t tf32r(float f) {
    uint32_t u; asm("cvt.rna.tf32.f32 %0, %1;" : "=r"(u) : "f"(f)); return u;
}
__device__ __forceinline__ float tf32f(float f) { return __uint_as_float(tf32r(f)); }
__device__ __forceinline__ uint32_t fau(float f) { return __float_as_uint(f); }

__device__ __forceinline__ void mma8(float* c, uint32_t a0, uint32_t a1, uint32_t a2, uint32_t a3,
                                     uint32_t b0, uint32_t b1) {
    asm volatile(
        "mma.sync.aligned.m16n8k8.row.col.f32.tf32.tf32.f32 "
        "{%0,%1,%2,%3},{%4,%5,%6,%7},{%8,%9},{%0,%1,%2,%3};"
        : "+f"(c[0]), "+f"(c[1]), "+f"(c[2]), "+f"(c[3])
        : "r"(a0), "r"(a1), "r"(a2), "r"(a3), "r"(b0), "r"(b1));
}

__device__ __forceinline__ void cp_async16(uint32_t saddr, const void* g) {
    asm volatile("cp.async.cg.shared.global [%0], [%1], 16;" :: "r"(saddr), "l"(g));
}

// ---------------------------------------------------------------------------
// Pre-pass kernels
// ---------------------------------------------------------------------------
__global__ void kprep_kernel(const float* __restrict__ K) {
    int idx = blockIdx.x * 256 + threadIdx.x;
    float v = K[idx];
    int d = idx & 63;
    int dst = (idx & ~63) | (d & ~7) | perm8(d & 7);
    g_Kc[dst] = tf32f(v);
}

__global__ void vtrans_kernel(const float* __restrict__ V) {
    __shared__ float t[64][65];
    int k0 = blockIdx.x * 64;
    int bh = blockIdx.y;
    const float* vp = V + ((size_t)bh * L + k0) * D;
    int tid = threadIdx.x;
#pragma unroll
    for (int i = 0; i < 16; ++i) {
        int e = i * 256 + tid;
        t[e >> 6][e & 63] = vp[e];
    }
    __syncthreads();
    float* op = g_Vt + (size_t)bh * D * L + k0;
#pragma unroll
    for (int i = 0; i < 16; ++i) {
        int e = i * 256 + tid;
        int d = e >> 6, c = e & 63;
        int key = (c & ~7) | iperm8(c & 7);
        op[(size_t)d * L + c] = tf32f(t[key][d]);
    }
}

__global__ void vmean_kernel(const float* __restrict__ V) {
    int bh = blockIdx.x;
    int d = threadIdx.x & 63;
    int c = threadIdx.x >> 6;
    __shared__ float part[4][64];
    const float* vp = V + (size_t)bh * L * D;
    float s = 0.f;
    for (int k = c * 512; k < c * 512 + 512; ++k) s += vp[(size_t)k * D + d];
    part[c][d] = s;
    __syncthreads();
    if (c == 0)
        g_vmean[bh * D + d] = (part[0][d] + part[1][d] + part[2][d] + part[3][d]) * (1.0f / 2048.0f);
}

// ---------------------------------------------------------------------------
// Main attention kernel: 4 warps, Q/P in registers, no-max softmax,
// double-buffered K/V AND bias via cp.async (bias DRAM latency off the chain)
// ---------------------------------------------------------------------------
__global__ __launch_bounds__(THREADS, 2)
void attn_kernel(const float* __restrict__ Q, const int* __restrict__ qmask,
                 const int* __restrict__ vmask, const float* __restrict__ bias,
                 float* __restrict__ out) {
    extern __shared__ float smem[];
    float* Ks[2] = { smem, smem + BK * PW };
    float* Vs[2] = { smem + 2 * BK * PW, smem + 3 * BK * PW };
    float* Bs[2] = { smem + 4 * BK * PW, smem + 4 * BK * PW + BQ * PB };

    const int qt = (NQT - 1) - blockIdx.x;        // big tiles first
    const int bh = blockIdx.y;
    const int q0 = qt * BQ;

    const float* Qg = Q + ((size_t)bh * L + q0) * D;
    const float* Kg = g_Kc + (size_t)bh * L * D;
    const float* Vg = g_Vt + (size_t)bh * D * L;
    const float* Bg = bias + ((size_t)bh * L + q0) * L;
    const int*  vmg = vmask + (size_t)bh * L;

    const int tid = threadIdx.x;
    const int w = tid >> 5, lane = tid & 31;
    const int g = lane >> 2, tig = lane & 3;

    const uint32_t sKs[2] = { (uint32_t)__cvta_generic_to_shared(Ks[0]),
                              (uint32_t)__cvta_generic_to_shared(Ks[1]) };
    const uint32_t sVs[2] = { (uint32_t)__cvta_generic_to_shared(Vs[0]),
                              (uint32_t)__cvta_generic_to_shared(Vs[1]) };
    const uint32_t sBs[2] = { (uint32_t)__cvta_generic_to_shared(Bs[0]),
                              (uint32_t)__cvta_generic_to_shared(Bs[1]) };

    const int nkt = qt + 1;

    // prefetch tile 0 (K, V, bias): each 64 rows x 16 16B-chunks = 8/thread
    {
#pragma unroll
        for (int i = 0; i < 8; ++i) {
            int c = tid + i * 128;
            int r = c >> 4, sg = (c & 15) * 4;
            cp_async16(sKs[0] + (uint32_t)(r * PW + sg) * 4, Kg + r * 64 + sg);
            cp_async16(sVs[0] + (uint32_t)(r * PW + sg) * 4, Vg + (size_t)r * L + sg);
            cp_async16(sBs[0] + (uint32_t)(r * PB + sg) * 4, Bg + (size_t)r * L + sg);
        }
        asm volatile("cp.async.commit_group;");
    }

    const int row0 = 16 * w + g;
    const int gq0 = q0 + row0, gq1 = gq0 + 8;

    // Q fragments in registers (scaled, tf32): reused across all k-tiles
    uint32_t qf[8][4];
    {
        const float* qr0 = Qg + (size_t)row0 * D;
        const float* qr1 = qr0 + 8 * D;
#pragma unroll
        for (int kk = 0; kk < 8; ++kk) {
            qf[kk][0] = tf32r(qr0[8 * kk + tig] * 0.125f);
            qf[kk][1] = tf32r(qr1[8 * kk + tig] * 0.125f);
            qf[kk][2] = tf32r(qr0[8 * kk + tig + 4] * 0.125f);
            qf[kk][3] = tf32r(qr1[8 * kk + tig + 4] * 0.125f);
        }
    }

    float o[8][4];
    float l0 = 0.f, l1 = 0.f;
#pragma unroll
    for (int j = 0; j < 8; ++j) { o[j][0] = o[j][1] = o[j][2] = o[j][3] = 0.f; }

    const int srcl = (lane & ~3) | (tig >> 1);     // P-conversion shuffle sources
    const int srcl2 = srcl + 2;
    const bool odd = tig & 1;

    for (int kt = 0; kt < nkt; ++kt) {
        const int k0 = kt * BK;
        const int buf = kt & 1;
        asm volatile("cp.async.wait_group 0;");
        __syncthreads();

        // prefetch next K/V/bias into other buffers (freed: all warps are past
        // the compute of iteration kt-1 which read them)
        if (kt + 1 < nkt) {
            const int nk0 = (kt + 1) * BK;
            const int nb = buf ^ 1;
#pragma unroll
            for (int i = 0; i < 8; ++i) {
                int c = tid + i * 128;
                int r = c >> 4, sg = (c & 15) * 4;
                cp_async16(sKs[nb] + (uint32_t)(r * PW + sg) * 4, Kg + (size_t)(nk0 + r) * 64 + sg);
                cp_async16(sVs[nb] + (uint32_t)(r * PW + sg) * 4, Vg + (size_t)r * L + nk0 + sg);
                cp_async16(sBs[nb] + (uint32_t)(r * PB + sg) * 4, Bg + (size_t)r * L + nk0 + sg);
            }
            asm volatile("cp.async.commit_group;");
        }

        uint32_t mw0 = __ballot_sync(0xffffffffu, vmg[k0 + lane] != 0);
        uint32_t mw1 = __ballot_sync(0xffffffffu, vmg[k0 + 32 + lane] != 0);
        const int lim0 = gq0 - k0, lim1 = lim0 + 8;

        // ---- S = Q K^T (A from regs) ----
        float s[8][4];
#pragma unroll
        for (int j = 0; j < 8; ++j) { s[j][0] = s[j][1] = s[j][2] = s[j][3] = 0.f; }
        const float* Kb = Ks[buf];
#pragma unroll
        for (int kk = 0; kk < 8; ++kk) {
            int co = 8 * kk + 2 * tig;
#pragma unroll
            for (int j = 0; j < 8; ++j) {
                float2 b = *(const float2*)(Kb + (8 * j + g) * PW + co);
                mma8(s[j], qf[kk][0], qf[kk][1], qf[kk][2], qf[kk][3], fau(b.x), fau(b.y));
            }
        }

        // ---- bias (from smem) + mask + exp (no-max) + C->A frag conversion ----
        const float* Bb0 = Bs[buf] + row0 * PB;
        const float* Bb1 = Bb0 + 8 * PB;
        uint32_t p[8][4];
#pragma unroll
        for (int j = 0; j < 8; ++j) {
            int c0 = 8 * j + 2 * tig;
            float2 bv0 = *(const float2*)(Bb0 + c0);
            float2 bv1 = *(const float2*)(Bb1 + c0);
            uint32_t mw = (c0 < 32) ? mw0 : mw1;
            bool mk0 = (mw >> (c0 & 31)) & 1u;
            bool mk1 = (mw >> ((c0 + 1) & 31)) & 1u;
            float e0 = (mk0 && c0     <= lim0) ? __expf(s[j][0] + bv0.x) : 0.f;
            float e1 = (mk1 && c0 + 1 <= lim0) ? __expf(s[j][1] + bv0.y) : 0.f;
            float e2 = (mk0 && c0     <= lim1) ? __expf(s[j][2] + bv1.x) : 0.f;
            float e3 = (mk1 && c0 + 1 <= lim1) ? __expf(s[j][3] + bv1.y) : 0.f;
            l0 += e0 + e1;
            l1 += e2 + e3;
            uint32_t r0 = tf32r(e0), r1 = tf32r(e1), r2 = tf32r(e2), r3 = tf32r(e3);
            uint32_t u0 = __shfl_sync(0xffffffffu, r0, srcl);
            uint32_t u1 = __shfl_sync(0xffffffffu, r1, srcl);
            uint32_t u2 = __shfl_sync(0xffffffffu, r2, srcl);
            uint32_t u3 = __shfl_sync(0xffffffffu, r3, srcl);
            uint32_t v0 = __shfl_sync(0xffffffffu, r0, srcl2);
            uint32_t v1 = __shfl_sync(0xffffffffu, r1, srcl2);
            uint32_t v2 = __shfl_sync(0xffffffffu, r2, srcl2);
            uint32_t v3 = __shfl_sync(0xffffffffu, r3, srcl2);
            p[j][0] = odd ? u1 : u0;   // (row g,   col tig)
            p[j][1] = odd ? u3 : u2;   // (row g+8, col tig)
            p[j][2] = odd ? v1 : v0;   // (row g,   col tig+4)
            p[j][3] = odd ? v3 : v2;   // (row g+8, col tig+4)
        }

        // ---- O += P V (A from regs) ----
        const float* Vb = Vs[buf];
#pragma unroll
        for (int kk = 0; kk < 8; ++kk) {
            int co = 8 * kk + 2 * tig;
#pragma unroll
            for (int j = 0; j < 8; ++j) {
                float2 b = *(const float2*)(Vb + (8 * j + g) * PW + co);
                mma8(o[j], p[kk][0], p[kk][1], p[kk][2], p[kk][3], fau(b.x), fau(b.y));
            }
        }
    }

    // ---- epilogue: deferred l reduction over the quad ----
    l0 += __shfl_xor_sync(0xffffffffu, l0, 1);
    l0 += __shfl_xor_sync(0xffffffffu, l0, 2);
    l1 += __shfl_xor_sync(0xffffffffu, l1, 1);
    l1 += __shfl_xor_sync(0xffffffffu, l1, 2);

    int qm0 = qmask[(size_t)bh * L + gq0];
    int qm1 = qmask[(size_t)bh * L + gq1];
    bool fm0 = (l0 == 0.f), fm1 = (l1 == 0.f);
    float il0 = fm0 ? 0.f : 1.0f / l0;
    float il1 = fm1 ? 0.f : 1.0f / l1;
#pragma unroll
    for (int j = 0; j < 8; ++j) {
        int c = 8 * j + 2 * tig;
        float2 r0, r1;
        r0.x = !qm0 ? 0.f : (fm0 ? g_vmean[bh * D + c]     : o[j][0] * il0);
        r0.y = !qm0 ? 0.f : (fm0 ? g_vmean[bh * D + c + 1] : o[j][1] * il0);
        r1.x = !qm1 ? 0.f : (fm1 ? g_vmean[bh * D + c]     : o[j][2] * il1);
        r1.y = !qm1 ? 0.f : (fm1 ? g_vmean[bh * D + c + 1] : o[j][3] * il1);
        *(float2*)(out + ((size_t)bh * L + gq0) * D + c) = r0;
        *(float2*)(out + ((size_t)bh * L + gq1) * D + c) = r1;
    }
}

// ---------------------------------------------------------------------------
extern "C" void kernel_launch(void* const* d_in, const int* in_sizes, int n_in,
                              void* d_out, int out_size) {
    const float* Q  = (const float*)d_in[0];
    const float* K  = (const float*)d_in[1];
    const float* V  = (const float*)d_in[2];
    const int* qm   = (const int*)d_in[3];
    const int* vm   = (const int*)d_in[4];
    const float* bi = (const float*)d_in[5];
    float* out = (float*)d_out;

    constexpr int SMEM_BYTES = (4 * BK * PW + 2 * BQ * PB) * (int)sizeof(float);  // 108544
    cudaFuncSetAttribute(attn_kernel, cudaFuncAttributeMaxDynamicSharedMemorySize, SMEM_BYTES);

    kprep_kernel<<<(B * H * L * D) / 256, 256>>>(K);
    vtrans_kernel<<<dim3(L / 64, B * H), 256>>>(V);
    vmean_kernel<<<B * H, 256>>>(V);
    attn_kernel<<<dim3(NQT, B * H), THREADS, SMEM_BYTES>>>(Q, qm, vm, bi, out);
}

// round 14
// speedup vs baseline: 1.0616x; 1.0071x over previous
#include <cuda_runtime.h>
#include <cuda_fp16.h>
#include <cstdint>

constexpr int B = 2, H = 16, L = 2048, D = 64;
constexpr int BQ = 64, BK = 64;
constexpr int PW = 72;                // K smem row stride (floats), conflict-free LDS.64
constexpr int PWH = 80;               // V smem row stride (halves): 160B rows, conflict-free LDS.32/64
constexpr int THREADS = 128;
constexpr int NQT = L / BQ;           // 32

// pre-converted operands
__device__ float  g_Kc[B * H * L * D];   // [bh][key][d']  tf32, d interleaved within 8-groups
__device__ __half g_Vh[B * H * D * L];   // [bh][d][key']  fp16, keys 16-group interleaved for k16 B-frags
__device__ float  g_vmean[B * H * D];

__device__ __forceinline__ int perm8(int k) { return 2 * (k & 3) + ((k >> 2) & 1); }
// within-16 key permutation: pairs (2t,2t+1) and (2t+8,2t+9) adjacent at pos 4t..4t+3
__device__ __forceinline__ int vperm16(int k) {
    int t = (k & 7) >> 1;
    return 4 * t + ((k >> 2) & 2) + (k & 1);
}

__device__ __forceinline__ uint32_t tf32r(float f) {
    uint32_t u; asm("cvt.rna.tf32.f32 %0, %1;" : "=r"(u) : "f"(f)); return u;
}
__device__ __forceinline__ float tf32f(float f) { return __uint_as_float(tf32r(f)); }
__device__ __forceinline__ uint32_t fau(float f) { return __float_as_uint(f); }

__device__ __forceinline__ void mma8(float* c, uint32_t a0, uint32_t a1, uint32_t a2, uint32_t a3,
                                     uint32_t b0, uint32_t b1) {
    asm volatile(
        "mma.sync.aligned.m16n8k8.row.col.f32.tf32.tf32.f32 "
        "{%0,%1,%2,%3},{%4,%5,%6,%7},{%8,%9},{%0,%1,%2,%3};"
        : "+f"(c[0]), "+f"(c[1]), "+f"(c[2]), "+f"(c[3])
        : "r"(a0), "r"(a1), "r"(a2), "r"(a3), "r"(b0), "r"(b1));
}

__device__ __forceinline__ void mma16h(float* c, uint32_t a0, uint32_t a1, uint32_t a2, uint32_t a3,
                                       uint32_t b0, uint32_t b1) {
    asm volatile(
        "mma.sync.aligned.m16n8k16.row.col.f32.f16.f16.f32 "
        "{%0,%1,%2,%3},{%4,%5,%6,%7},{%8,%9},{%0,%1,%2,%3};"
        : "+f"(c[0]), "+f"(c[1]), "+f"(c[2]), "+f"(c[3])
        : "r"(a0), "r"(a1), "r"(a2), "r"(a3), "r"(b0), "r"(b1));
}

__device__ __forceinline__ void cp_async16(uint32_t saddr, const void* g) {
    asm volatile("cp.async.cg.shared.global [%0], [%1], 16;" :: "r"(saddr), "l"(g));
}

__device__ __forceinline__ uint32_t packh2(float a, float b) {
    __half2 h = __floats2half2_rn(a, b);
    return *reinterpret_cast<uint32_t*>(&h);
}

// ---------------------------------------------------------------------------
// Pre-pass kernels
// ---------------------------------------------------------------------------
__global__ void kprep_kernel(const float* __restrict__ K) {
    int idx = blockIdx.x * 256 + threadIdx.x;
    float v = K[idx];
    int d = idx & 63;
    int dst = (idx & ~63) | (d & ~7) | perm8(d & 7);
    g_Kc[dst] = tf32f(v);
}

__global__ void vtrans_kernel(const float* __restrict__ V) {
    __shared__ float t[64][65];
    int k0 = blockIdx.x * 64;
    int bh = blockIdx.y;
    const float* vp = V + ((size_t)bh * L + k0) * D;
    int tid = threadIdx.x;
#pragma unroll
    for (int i = 0; i < 16; ++i) {
        int e = i * 256 + tid;
        t[e >> 6][e & 63] = vp[e];
    }
    __syncthreads();
    __half* op = g_Vh + (size_t)bh * D * L + k0;
#pragma unroll
    for (int i = 0; i < 16; ++i) {
        int e = i * 256 + tid;
        int d = e >> 6, key = e & 63;                // transpose + interleave on write
        int pos = (key & ~15) | vperm16(key & 15);
        op[(size_t)d * L + pos] = __float2half_rn(t[key][d]);
    }
}

__global__ void vmean_kernel(const float* __restrict__ V) {
    int bh = blockIdx.x;
    int d = threadIdx.x & 63;
    int c = threadIdx.x >> 6;
    __shared__ float part[4][64];
    const float* vp = V + (size_t)bh * L * D;
    float s = 0.f;
    for (int k = c * 512; k < c * 512 + 512; ++k) s += vp[(size_t)k * D + d];
    part[c][d] = s;
    __syncthreads();
    if (c == 0)
        g_vmean[bh * D + d] = (part[0][d] + part[1][d] + part[2][d] + part[3][d]) * (1.0f / 2048.0f);
}

// ---------------------------------------------------------------------------
// Main attention kernel: tf32 S-GEMM + fp16 PV-GEMM (shuffle-free P),
// online softmax, double-buffered K/V, 3 CTAs/SM
// ---------------------------------------------------------------------------
__global__ __launch_bounds__(THREADS, 3)
void attn_kernel(const float* __restrict__ Q, const int* __restrict__ qmask,
                 const int* __restrict__ vmask, const float* __restrict__ bias,
                 float* __restrict__ out) {
    extern __shared__ float smem[];
    constexpr int KT = BK * PW;                     // floats per K tile
    float*  Ks[2] = { smem, smem + KT };
    __half* Vs[2] = { (__half*)(smem + 2 * KT), (__half*)(smem + 2 * KT) + BK * PWH };

    const int qt = (NQT - 1) - blockIdx.x;          // big tiles first
    const int bh = blockIdx.y;
    const int q0 = qt * BQ;

    const float*  Qg = Q + ((size_t)bh * L + q0) * D;
    const float*  Kg = g_Kc + (size_t)bh * L * D;
    const __half* Vg = g_Vh + (size_t)bh * D * L;
    const float*  Bg = bias + ((size_t)bh * L + q0) * L;
    const int*   vmg = vmask + (size_t)bh * L;

    const int tid = threadIdx.x;
    const int w = tid >> 5, lane = tid & 31;
    const int g = lane >> 2, tig = lane & 3;

    const uint32_t sKs[2] = { (uint32_t)__cvta_generic_to_shared(Ks[0]),
                              (uint32_t)__cvta_generic_to_shared(Ks[1]) };
    const uint32_t sVs[2] = { (uint32_t)__cvta_generic_to_shared(Vs[0]),
                              (uint32_t)__cvta_generic_to_shared(Vs[1]) };

    const int nkt = qt + 1;

    // prefetch tile 0: K 64rows x 16 chunks (8/thread); V 64rows x 8 chunks (4/thread)
    {
#pragma unroll
        for (int i = 0; i < 8; ++i) {
            int c = tid + i * 128;
            int r = c >> 4, sg = (c & 15) * 4;
            cp_async16(sKs[0] + (uint32_t)(r * PW + sg) * 4, Kg + r * 64 + sg);
        }
#pragma unroll
        for (int i = 0; i < 4; ++i) {
            int c = tid + i * 128;
            int r = c >> 3, sg = (c & 7) * 8;       // 8 halves per 16B chunk
            cp_async16(sVs[0] + (uint32_t)(r * PWH + sg) * 2, Vg + (size_t)r * L + sg);
        }
        asm volatile("cp.async.commit_group;");
    }

    const int row0 = 16 * w + g;
    const int gq0 = q0 + row0, gq1 = gq0 + 8;

    // Q fragments in registers (scaled, tf32)
    uint32_t qf[8][4];
    {
        const float* qr0 = Qg + (size_t)row0 * D;
        const float* qr1 = qr0 + 8 * D;
#pragma unroll
        for (int kk = 0; kk < 8; ++kk) {
            qf[kk][0] = tf32r(qr0[8 * kk + tig] * 0.125f);
            qf[kk][1] = tf32r(qr1[8 * kk + tig] * 0.125f);
            qf[kk][2] = tf32r(qr0[8 * kk + tig + 4] * 0.125f);
            qf[kk][3] = tf32r(qr1[8 * kk + tig + 4] * 0.125f);
        }
    }

    float o[8][4];
    float l0 = 0.f, l1 = 0.f, m0 = -1e30f, m1 = -1e30f;
#pragma unroll
    for (int j = 0; j < 8; ++j) { o[j][0] = o[j][1] = o[j][2] = o[j][3] = 0.f; }

    for (int kt = 0; kt < nkt; ++kt) {
        const int k0 = kt * BK;
        const int buf = kt & 1;
        asm volatile("cp.async.wait_group 0;");
        __syncthreads();

        if (kt + 1 < nkt) {
            const int nk0 = (kt + 1) * BK;
            const int nb = buf ^ 1;
#pragma unroll
            for (int i = 0; i < 8; ++i) {
                int c = tid + i * 128;
                int r = c >> 4, sg = (c & 15) * 4;
                cp_async16(sKs[nb] + (uint32_t)(r * PW + sg) * 4, Kg + (size_t)(nk0 + r) * 64 + sg);
            }
#pragma unroll
            for (int i = 0; i < 4; ++i) {
                int c = tid + i * 128;
                int r = c >> 3, sg = (c & 7) * 8;
                cp_async16(sVs[nb] + (uint32_t)(r * PWH + sg) * 2, Vg + (size_t)r * L + nk0 + sg);
            }
            asm volatile("cp.async.commit_group;");
        }

        // bias + mask prefetch (in flight during S-mma)
        float2 bv0[8], bv1[8];
#pragma unroll
        for (int j = 0; j < 8; ++j) {
            int c0 = k0 + 8 * j + 2 * tig;
            bv0[j] = *(const float2*)(Bg + (size_t)row0 * L + c0);
            bv1[j] = *(const float2*)(Bg + (size_t)(row0 + 8) * L + c0);
        }
        uint32_t mw0 = __ballot_sync(0xffffffffu, vmg[k0 + lane] != 0);
        uint32_t mw1 = __ballot_sync(0xffffffffu, vmg[k0 + 32 + lane] != 0);
        const int lim0 = gq0 - k0, lim1 = lim0 + 8;

        // ---- S = Q K^T (tf32, A from regs) ----
        float s[8][4];
#pragma unroll
        for (int j = 0; j < 8; ++j) { s[j][0] = s[j][1] = s[j][2] = s[j][3] = 0.f; }
        const float* Kb = Ks[buf];
#pragma unroll
        for (int kk = 0; kk < 8; ++kk) {
            int co = 8 * kk + 2 * tig;
#pragma unroll
            for (int j = 0; j < 8; ++j) {
                float2 b = *(const float2*)(Kb + (8 * j + g) * PW + co);
                mma8(s[j], qf[kk][0], qf[kk][1], qf[kk][2], qf[kk][3], fau(b.x), fau(b.y));
            }
        }

        // ---- scores + validity; tile max over valid ----
        bool v0[8], v1[8], v2[8], v3[8];
        float tm0 = -1e30f, tm1 = -1e30f;
#pragma unroll
        for (int j = 0; j < 8; ++j) {
            int c0 = 8 * j + 2 * tig;
            uint32_t mw = (c0 < 32) ? mw0 : mw1;
            bool mk0 = (mw >> (c0 & 31)) & 1u;
            bool mk1 = (mw >> ((c0 + 1) & 31)) & 1u;
            v0[j] = mk0 && (c0     <= lim0);
            v1[j] = mk1 && (c0 + 1 <= lim0);
            v2[j] = mk0 && (c0     <= lim1);
            v3[j] = mk1 && (c0 + 1 <= lim1);
            s[j][0] += bv0[j].x; s[j][1] += bv0[j].y;
            s[j][2] += bv1[j].x; s[j][3] += bv1[j].y;
            tm0 = fmaxf(tm0, fmaxf(v0[j] ? s[j][0] : -1e30f, v1[j] ? s[j][1] : -1e30f));
            tm1 = fmaxf(tm1, fmaxf(v2[j] ? s[j][2] : -1e30f, v3[j] ? s[j][3] : -1e30f));
        }
        tm0 = fmaxf(tm0, __shfl_xor_sync(0xffffffffu, tm0, 1));
        tm0 = fmaxf(tm0, __shfl_xor_sync(0xffffffffu, tm0, 2));
        tm1 = fmaxf(tm1, __shfl_xor_sync(0xffffffffu, tm1, 1));
        tm1 = fmaxf(tm1, __shfl_xor_sync(0xffffffffu, tm1, 2));
        float nm0 = fmaxf(m0, tm0), nm1 = fmaxf(m1, tm1);
        float al0 = __expf(m0 - nm0), al1 = __expf(m1 - nm1);
        m0 = nm0; m1 = nm1;

        // ---- exp + pack P directly into fp16 A-fragments (no shuffles) ----
        uint32_t p[4][4];
        float a0s = 0.f, a1s = 0.f;
#pragma unroll
        for (int j = 0; j < 8; ++j) {
            float e0 = v0[j] ? __expf(s[j][0] - m0) : 0.f;
            float e1 = v1[j] ? __expf(s[j][1] - m0) : 0.f;
            float e2 = v2[j] ? __expf(s[j][2] - m1) : 0.f;
            float e3 = v3[j] ? __expf(s[j][3] - m1) : 0.f;
            a0s += e0 + e1;
            a1s += e2 + e3;
            int kk = j >> 1;
            if ((j & 1) == 0) {
                p[kk][0] = packh2(e0, e1);   // rows g,   k=2tig..+1  (cols 16kk+)
                p[kk][1] = packh2(e2, e3);   // rows g+8
            } else {
                p[kk][2] = packh2(e0, e1);   // rows g,   k=2tig+8..+9
                p[kk][3] = packh2(e2, e3);   // rows g+8
            }
        }
        l0 = l0 * al0 + a0s;
        l1 = l1 * al1 + a1s;

        // ---- rescale O, then O += P V (fp16 m16n8k16) ----
        const __half* Vb = Vs[buf];
#pragma unroll
        for (int j = 0; j < 8; ++j) {
            o[j][0] *= al0; o[j][1] *= al0; o[j][2] *= al1; o[j][3] *= al1;
        }
#pragma unroll
        for (int kk = 0; kk < 4; ++kk) {
            int co = 16 * kk + 4 * tig;              // interleaved key pos (halves)
#pragma unroll
            for (int j = 0; j < 8; ++j) {
                const __half* vr = Vb + (8 * j + g) * PWH + co;
                uint32_t b0 = *(const uint32_t*)(vr);        // keys 2tig,2tig+1
                uint32_t b1 = *(const uint32_t*)(vr + 2);    // keys 2tig+8,2tig+9
                mma16h(o[j], p[kk][0], p[kk][1], p[kk][2], p[kk][3], b0, b1);
            }
        }
    }

    // ---- epilogue: deferred l reduction over the quad ----
    l0 += __shfl_xor_sync(0xffffffffu, l0, 1);
    l0 += __shfl_xor_sync(0xffffffffu, l0, 2);
    l1 += __shfl_xor_sync(0xffffffffu, l1, 1);
    l1 += __shfl_xor_sync(0xffffffffu, l1, 2);

    int qm0 = qmask[(size_t)bh * L + gq0];
    int qm1 = qmask[(size_t)bh * L + gq1];
    bool fm0 = (l0 == 0.f), fm1 = (l1 == 0.f);
    float il0 = fm0 ? 0.f : 1.0f / l0;
    float il1 = fm1 ? 0.f : 1.0f / l1;
#pragma unroll
    for (int j = 0; j < 8; ++j) {
        int c = 8 * j + 2 * tig;
        float2 r0, r1;
        r0.x = !qm0 ? 0.f : (fm0 ? g_vmean[bh * D + c]     : o[j][0] * il0);
        r0.y = !qm0 ? 0.f : (fm0 ? g_vmean[bh * D + c + 1] : o[j][1] * il0);
        r1.x = !qm1 ? 0.f : (fm1 ? g_vmean[bh * D + c]     : o[j][2] * il1);
        r1.y = !qm1 ? 0.f : (fm1 ? g_vmean[bh * D + c + 1] : o[j][3] * il1);
        *(float2*)(out + ((size_t)bh * L + gq0) * D + c) = r0;
        *(float2*)(out + ((size_t)bh * L + gq1) * D + c) = r1;
    }
}

// ---------------------------------------------------------------------------
extern "C" void kernel_launch(void* const* d_in, const int* in_sizes, int n_in,
                              void* d_out, int out_size) {
    const float* Q  = (const float*)d_in[0];
    const float* K  = (const float*)d_in[1];
    const float* V  = (const float*)d_in[2];
    const int* qm   = (const int*)d_in[3];
    const int* vm   = (const int*)d_in[4];
    const float* bi = (const float*)d_in[5];
    float* out = (float*)d_out;

    constexpr int SMEM_BYTES = 2 * BK * PW * 4 + 2 * BK * PWH * 2;   // 36864 + 20480 = 57344
    cudaFuncSetAttribute(attn_kernel, cudaFuncAttributeMaxDynamicSharedMemorySize, SMEM_BYTES);

    kprep_kernel<<<(B * H * L * D) / 256, 256>>>(K);
    vtrans_kernel<<<dim3(L / 64, B * H), 256>>>(V);
    vmean_kernel<<<B * H, 256>>>(V);
    attn_kernel<<<dim3(NQT, B * H), THREADS, SMEM_BYTES>>>(Q, qm, vm, bi, out);
}

// round 15
// speedup vs baseline: 1.3800x; 1.3000x over previous
#include <cuda_runtime.h>
#include <cuda_fp16.h>
#include <cstdint>

constexpr int B = 2, H = 16, L = 2048, D = 64;
constexpr int BQ = 64, BK = 64;
constexpr int PWH = 80;               // smem row stride (halves): 160B rows, LDS.64 conflict-free
constexpr int THREADS = 128;
constexpr int NQT = L / BQ;           // 32
constexpr float SCL = 0.18033688011112042f;      // 0.125 * log2(e)
constexpr float LOG2E = 1.4426950408889634f;

// pre-converted fp16 operands, 16-group interleaved for m16n8k16 B-fragments
__device__ __half g_Kh[B * H * L * D];   // [bh][key][d']
__device__ __half g_Vh[B * H * D * L];   // [bh][d][key']
__device__ float  g_vmean[B * H * D];

// within-16 permutation: pos 4t..4t+3 hold elements {2t, 2t+1, 2t+8, 2t+9}
__device__ __forceinline__ int vperm16(int k) {
    int t = (k & 7) >> 1;
    return 4 * t + ((k >> 2) & 2) + (k & 1);
}

__device__ __forceinline__ void mma16h(float* c, uint32_t a0, uint32_t a1, uint32_t a2, uint32_t a3,
                                       uint32_t b0, uint32_t b1) {
    asm volatile(
        "mma.sync.aligned.m16n8k16.row.col.f32.f16.f16.f32 "
        "{%0,%1,%2,%3},{%4,%5,%6,%7},{%8,%9},{%0,%1,%2,%3};"
        : "+f"(c[0]), "+f"(c[1]), "+f"(c[2]), "+f"(c[3])
        : "r"(a0), "r"(a1), "r"(a2), "r"(a3), "r"(b0), "r"(b1));
}

__device__ __forceinline__ void cp_async16(uint32_t saddr, const void* g) {
    asm volatile("cp.async.cg.shared.global [%0], [%1], 16;" :: "r"(saddr), "l"(g));
}

__device__ __forceinline__ uint32_t packh2(float a, float b) {
    __half2 h = __floats2half2_rn(a, b);
    return *reinterpret_cast<uint32_t*>(&h);
}

__device__ __forceinline__ float ex2(float x) {
    float y; asm("ex2.approx.ftz.f32 %0, %1;" : "=f"(y) : "f"(x)); return y;
}

// ---------------------------------------------------------------------------
// Pre-pass kernels
// ---------------------------------------------------------------------------
__global__ void kprep_kernel(const float* __restrict__ K) {
    int idx = blockIdx.x * 256 + threadIdx.x;
    int d = idx & 63;
    int dst = (idx & ~63) | (d & ~15) | vperm16(d & 15);
    g_Kh[dst] = __float2half_rn(K[idx]);
}

__global__ void vtrans_kernel(const float* __restrict__ V) {
    __shared__ float t[64][65];
    int k0 = blockIdx.x * 64;
    int bh = blockIdx.y;
    const float* vp = V + ((size_t)bh * L + k0) * D;
    int tid = threadIdx.x;
#pragma unroll
    for (int i = 0; i < 16; ++i) {
        int e = i * 256 + tid;
        t[e >> 6][e & 63] = vp[e];
    }
    __syncthreads();
    __half* op = g_Vh + (size_t)bh * D * L + k0;
#pragma unroll
    for (int i = 0; i < 16; ++i) {
        int e = i * 256 + tid;
        int d = e >> 6, key = e & 63;                // transpose + interleave on write
        int pos = (key & ~15) | vperm16(key & 15);
        op[(size_t)d * L + pos] = __float2half_rn(t[key][d]);
    }
}

__global__ void vmean_kernel(const float* __restrict__ V) {
    int bh = blockIdx.x;
    int d = threadIdx.x & 63;
    int c = threadIdx.x >> 6;
    __shared__ float part[4][64];
    const float* vp = V + (size_t)bh * L * D;
    float s = 0.f;
    for (int k = c * 512; k < c * 512 + 512; ++k) s += vp[(size_t)k * D + d];
    part[c][d] = s;
    __syncthreads();
    if (c == 0)
        g_vmean[bh * D + d] = (part[0][d] + part[1][d] + part[2][d] + part[3][d]) * (1.0f / 2048.0f);
}

// ---------------------------------------------------------------------------
// Main attention kernel: fp16 S-GEMM + fp16 PV-GEMM, log2-domain online
// softmax, Q/P fragments in registers, double-buffered K/V, 3 CTAs/SM
// ---------------------------------------------------------------------------
__global__ __launch_bounds__(THREADS, 3)
void attn_kernel(const float* __restrict__ Q, const int* __restrict__ qmask,
                 const int* __restrict__ vmask, const float* __restrict__ bias,
                 float* __restrict__ out) {
    extern __shared__ __half smem[];
    constexpr int HT = BK * PWH;                    // halves per tile
    __half* Ks[2] = { smem, smem + HT };
    __half* Vs[2] = { smem + 2 * HT, smem + 3 * HT };

    const int qt = (NQT - 1) - blockIdx.x;          // big tiles first
    const int bh = blockIdx.y;
    const int q0 = qt * BQ;

    const float*  Qg = Q + ((size_t)bh * L + q0) * D;
    const __half* Kg = g_Kh + (size_t)bh * L * D;
    const __half* Vg = g_Vh + (size_t)bh * D * L;
    const float*  Bg = bias + ((size_t)bh * L + q0) * L;
    const int*   vmg = vmask + (size_t)bh * L;

    const int tid = threadIdx.x;
    const int w = tid >> 5, lane = tid & 31;
    const int g = lane >> 2, tig = lane & 3;

    const uint32_t sKs[2] = { (uint32_t)__cvta_generic_to_shared(Ks[0]),
                              (uint32_t)__cvta_generic_to_shared(Ks[1]) };
    const uint32_t sVs[2] = { (uint32_t)__cvta_generic_to_shared(Vs[0]),
                              (uint32_t)__cvta_generic_to_shared(Vs[1]) };

    const int nkt = qt + 1;

    // prefetch tile 0: K and V each 64 rows x 8 16B-chunks = 4 chunks/thread
    {
#pragma unroll
        for (int i = 0; i < 4; ++i) {
            int c = tid + i * 128;
            int r = c >> 3, sg = (c & 7) * 8;       // 8 halves per chunk
            cp_async16(sKs[0] + (uint32_t)(r * PWH + sg) * 2, Kg + (size_t)r * 64 + sg);
            cp_async16(sVs[0] + (uint32_t)(r * PWH + sg) * 2, Vg + (size_t)r * L + sg);
        }
        asm volatile("cp.async.commit_group;");
    }

    const int row0 = 16 * w + g;
    const int gq0 = q0 + row0, gq1 = gq0 + 8;

    // Q fragments in registers (scaled by 0.125*log2e, fp16, m16n8k16 A layout)
    uint32_t qf[4][4];
    {
        const float* qr0 = Qg + (size_t)row0 * D;
        const float* qr1 = qr0 + 8 * D;
#pragma unroll
        for (int kk = 0; kk < 4; ++kk) {
            int c0 = 16 * kk + 2 * tig;
            qf[kk][0] = packh2(qr0[c0] * SCL, qr0[c0 + 1] * SCL);
            qf[kk][1] = packh2(qr1[c0] * SCL, qr1[c0 + 1] * SCL);
            qf[kk][2] = packh2(qr0[c0 + 8] * SCL, qr0[c0 + 9] * SCL);
            qf[kk][3] = packh2(qr1[c0 + 8] * SCL, qr1[c0 + 9] * SCL);
        }
    }

    float o[8][4];
    float l0 = 0.f, l1 = 0.f, m0 = -1e30f, m1 = -1e30f;   // log2-domain
#pragma unroll
    for (int j = 0; j < 8; ++j) { o[j][0] = o[j][1] = o[j][2] = o[j][3] = 0.f; }

    for (int kt = 0; kt < nkt; ++kt) {
        const int k0 = kt * BK;
        const int buf = kt & 1;
        asm volatile("cp.async.wait_group 0;");
        __syncthreads();

        if (kt + 1 < nkt) {
            const int nk0 = (kt + 1) * BK;
            const int nb = buf ^ 1;
#pragma unroll
            for (int i = 0; i < 4; ++i) {
                int c = tid + i * 128;
                int r = c >> 3, sg = (c & 7) * 8;
                cp_async16(sKs[nb] + (uint32_t)(r * PWH + sg) * 2, Kg + (size_t)(nk0 + r) * 64 + sg);
                cp_async16(sVs[nb] + (uint32_t)(r * PWH + sg) * 2, Vg + (size_t)r * L + nk0 + sg);
            }
            asm volatile("cp.async.commit_group;");
        }

        // bias + mask prefetch (in flight during S-mma)
        float2 bv0[8], bv1[8];
#pragma unroll
        for (int j = 0; j < 8; ++j) {
            int c0 = k0 + 8 * j + 2 * tig;
            bv0[j] = *(const float2*)(Bg + (size_t)row0 * L + c0);
            bv1[j] = *(const float2*)(Bg + (size_t)(row0 + 8) * L + c0);
        }
        uint32_t mw0 = __ballot_sync(0xffffffffu, vmg[k0 + lane] != 0);
        uint32_t mw1 = __ballot_sync(0xffffffffu, vmg[k0 + 32 + lane] != 0);
        const int lim0 = gq0 - k0, lim1 = lim0 + 8;

        // ---- S = Q K^T (fp16 m16n8k16, A from regs, B one LDS.64 each) ----
        float s[8][4];
#pragma unroll
        for (int j = 0; j < 8; ++j) { s[j][0] = s[j][1] = s[j][2] = s[j][3] = 0.f; }
        const __half* Kb = Ks[buf];
#pragma unroll
        for (int kk = 0; kk < 4; ++kk) {
            int co = 16 * kk + 4 * tig;              // interleaved d pos (halves)
#pragma unroll
            for (int j = 0; j < 8; ++j) {
                uint2 b = *(const uint2*)(Kb + (8 * j + g) * PWH + co);
                mma16h(s[j], qf[kk][0], qf[kk][1], qf[kk][2], qf[kk][3], b.x, b.y);
            }
        }

        // ---- bias (FFMA with log2e) + validity; tile max over valid ----
        bool v0[8], v1[8], v2[8], v3[8];
        float tm0 = -1e30f, tm1 = -1e30f;
#pragma unroll
        for (int j = 0; j < 8; ++j) {
            int c0 = 8 * j + 2 * tig;
            uint32_t mw = (c0 < 32) ? mw0 : mw1;
            bool mk0 = (mw >> (c0 & 31)) & 1u;
            bool mk1 = (mw >> ((c0 + 1) & 31)) & 1u;
            v0[j] = mk0 && (c0     <= lim0);
            v1[j] = mk1 && (c0 + 1 <= lim0);
            v2[j] = mk0 && (c0     <= lim1);
            v3[j] = mk1 && (c0 + 1 <= lim1);
            s[j][0] = fmaf(bv0[j].x, LOG2E, s[j][0]);
            s[j][1] = fmaf(bv0[j].y, LOG2E, s[j][1]);
            s[j][2] = fmaf(bv1[j].x, LOG2E, s[j][2]);
            s[j][3] = fmaf(bv1[j].y, LOG2E, s[j][3]);
            tm0 = fmaxf(tm0, fmaxf(v0[j] ? s[j][0] : -1e30f, v1[j] ? s[j][1] : -1e30f));
            tm1 = fmaxf(tm1, fmaxf(v2[j] ? s[j][2] : -1e30f, v3[j] ? s[j][3] : -1e30f));
        }
        tm0 = fmaxf(tm0, __shfl_xor_sync(0xffffffffu, tm0, 1));
        tm0 = fmaxf(tm0, __shfl_xor_sync(0xffffffffu, tm0, 2));
        tm1 = fmaxf(tm1, __shfl_xor_sync(0xffffffffu, tm1, 1));
        tm1 = fmaxf(tm1, __shfl_xor_sync(0xffffffffu, tm1, 2));
        float nm0 = fmaxf(m0, tm0), nm1 = fmaxf(m1, tm1);
        float al0 = ex2(m0 - nm0), al1 = ex2(m1 - nm1);
        m0 = nm0; m1 = nm1;

        // ---- exp2 + pack P directly into fp16 A-fragments ----
        uint32_t p[4][4];
        float a0s = 0.f, a1s = 0.f;
#pragma unroll
        for (int j = 0; j < 8; ++j) {
            float e0 = v0[j] ? ex2(s[j][0] - m0) : 0.f;
            float e1 = v1[j] ? ex2(s[j][1] - m0) : 0.f;
            float e2 = v2[j] ? ex2(s[j][2] - m1) : 0.f;
            float e3 = v3[j] ? ex2(s[j][3] - m1) : 0.f;
            a0s += e0 + e1;
            a1s += e2 + e3;
            int kk = j >> 1;
            if ((j & 1) == 0) {
                p[kk][0] = packh2(e0, e1);   // rows g,   keys 16kk+2tig..+1
                p[kk][1] = packh2(e2, e3);   // rows g+8
            } else {
                p[kk][2] = packh2(e0, e1);   // rows g,   keys 16kk+2tig+8..+9
                p[kk][3] = packh2(e2, e3);   // rows g+8
            }
        }
        l0 = l0 * al0 + a0s;
        l1 = l1 * al1 + a1s;

        // ---- rescale O, then O += P V (fp16 m16n8k16) ----
        const __half* Vb = Vs[buf];
#pragma unroll
        for (int j = 0; j < 8; ++j) {
            o[j][0] *= al0; o[j][1] *= al0; o[j][2] *= al1; o[j][3] *= al1;
        }
#pragma unroll
        for (int kk = 0; kk < 4; ++kk) {
            int co = 16 * kk + 4 * tig;              // interleaved key pos (halves)
#pragma unroll
            for (int j = 0; j < 8; ++j) {
                uint2 b = *(const uint2*)(Vb + (8 * j + g) * PWH + co);
                mma16h(o[j], p[kk][0], p[kk][1], p[kk][2], p[kk][3], b.x, b.y);
            }
        }
    }

    // ---- epilogue: deferred l reduction over the quad ----
    l0 += __shfl_xor_sync(0xffffffffu, l0, 1);
    l0 += __shfl_xor_sync(0xffffffffu, l0, 2);
    l1 += __shfl_xor_sync(0xffffffffu, l1, 1);
    l1 += __shfl_xor_sync(0xffffffffu, l1, 2);

    int qm0 = qmask[(size_t)bh * L + gq0];
    int qm1 = qmask[(size_t)bh * L + gq1];
    bool fm0 = (l0 == 0.f), fm1 = (l1 == 0.f);
    float il0 = fm0 ? 0.f : 1.0f / l0;
    float il1 = fm1 ? 0.f : 1.0f / l1;
#pragma unroll
    for (int j = 0; j < 8; ++j) {
        int c = 8 * j + 2 * tig;
        float2 r0, r1;
        r0.x = !qm0 ? 0.f : (fm0 ? g_vmean[bh * D + c]     : o[j][0] * il0);
        r0.y = !qm0 ? 0.f : (fm0 ? g_vmean[bh * D + c + 1] : o[j][1] * il0);
        r1.x = !qm1 ? 0.f : (fm1 ? g_vmean[bh * D + c]     : o[j][2] * il1);
        r1.y = !qm1 ? 0.f : (fm1 ? g_vmean[bh * D + c + 1] : o[j][3] * il1);
        *(float2*)(out + ((size_t)bh * L + gq0) * D + c) = r0;
        *(float2*)(out + ((size_t)bh * L + gq1) * D + c) = r1;
    }
}

// ---------------------------------------------------------------------------
extern "C" void kernel_launch(void* const* d_in, const int* in_sizes, int n_in,
                              void* d_out, int out_size) {
    const float* Q  = (const float*)d_in[0];
    const float* K  = (const float*)d_in[1];
    const float* V  = (const float*)d_in[2];
    const int* qm   = (const int*)d_in[3];
    const int* vm   = (const int*)d_in[4];
    const float* bi = (const float*)d_in[5];
    float* out = (float*)d_out;

    constexpr int SMEM_BYTES = 4 * BK * PWH * 2;   // 40960
    cudaFuncSetAttribute(attn_kernel, cudaFuncAttributeMaxDynamicSharedMemorySize, SMEM_BYTES);

    kprep_kernel<<<(B * H * L * D) / 256, 256>>>(K);
    vtrans_kernel<<<dim3(L / 64, B * H), 256>>>(V);
    vmean_kernel<<<B * H, 256>>>(V);
    attn_kernel<<<dim3(NQT, B * H), THREADS, SMEM_BYTES>>>(Q, qm, vm, bi, out);
}

// round 16
// speedup vs baseline: 1.4782x; 1.0712x over previous
#include <cuda_runtime.h>
#include <cuda_fp16.h>
#include <cstdint>

constexpr int B = 2, H = 16, L = 2048, D = 64;
constexpr int BQ = 64, BK = 64;
constexpr int PWH = 80;               // K/V smem row stride (halves): 160B rows, LDS.64 conflict-free
constexpr int PB = 68;                // bias smem row stride (floats)
constexpr int THREADS = 128;
constexpr int NQT = L / BQ;           // 32
constexpr float SCL = 0.18033688011112042f;      // 0.125 * log2(e)
constexpr float LOG2E = 1.4426950408889634f;

// pre-converted fp16 operands, 16-group interleaved for m16n8k16 B-fragments
__device__ __half g_Kh[B * H * L * D];   // [bh][key][d']
__device__ __half g_Vh[B * H * D * L];   // [bh][d][key']
__device__ float  g_vmean[B * H * D];

// within-16 permutation: pos 4t..4t+3 hold elements {2t, 2t+1, 2t+8, 2t+9}
__device__ __forceinline__ int vperm16(int k) {
    int t = (k & 7) >> 1;
    return 4 * t + ((k >> 2) & 2) + (k & 1);
}

__device__ __forceinline__ void mma16h(float* c, uint32_t a0, uint32_t a1, uint32_t a2, uint32_t a3,
                                       uint32_t b0, uint32_t b1) {
    asm volatile(
        "mma.sync.aligned.m16n8k16.row.col.f32.f16.f16.f32 "
        "{%0,%1,%2,%3},{%4,%5,%6,%7},{%8,%9},{%0,%1,%2,%3};"
        : "+f"(c[0]), "+f"(c[1]), "+f"(c[2]), "+f"(c[3])
        : "r"(a0), "r"(a1), "r"(a2), "r"(a3), "r"(b0), "r"(b1));
}

__device__ __forceinline__ void cp_async16(uint32_t saddr, const void* g) {
    asm volatile("cp.async.cg.shared.global [%0], [%1], 16;" :: "r"(saddr), "l"(g));
}

__device__ __forceinline__ uint32_t packh2(float a, float b) {
    __half2 h = __floats2half2_rn(a, b);
    return *reinterpret_cast<uint32_t*>(&h);
}

__device__ __forceinline__ float ex2(float x) {
    float y; asm("ex2.approx.ftz.f32 %0, %1;" : "=f"(y) : "f"(x)); return y;
}

// ---------------------------------------------------------------------------
// Pre-pass kernels
// ---------------------------------------------------------------------------
__global__ void kprep_kernel(const float* __restrict__ K) {
    int idx = blockIdx.x * 256 + threadIdx.x;
    int d = idx & 63;
    int dst = (idx & ~63) | (d & ~15) | vperm16(d & 15);
    g_Kh[dst] = __float2half_rn(K[idx]);
}

__global__ void vtrans_kernel(const float* __restrict__ V) {
    __shared__ float t[64][65];
    int k0 = blockIdx.x * 64;
    int bh = blockIdx.y;
    const float* vp = V + ((size_t)bh * L + k0) * D;
    int tid = threadIdx.x;
#pragma unroll
    for (int i = 0; i < 16; ++i) {
        int e = i * 256 + tid;
        t[e >> 6][e & 63] = vp[e];
    }
    __syncthreads();
    __half* op = g_Vh + (size_t)bh * D * L + k0;
#pragma unroll
    for (int i = 0; i < 16; ++i) {
        int e = i * 256 + tid;
        int d = e >> 6, key = e & 63;                // transpose + interleave on write
        int pos = (key & ~15) | vperm16(key & 15);
        op[(size_t)d * L + pos] = __float2half_rn(t[key][d]);
    }
}

__global__ void vmean_kernel(const float* __restrict__ V) {
    int bh = blockIdx.x;
    int d = threadIdx.x & 63;
    int c = threadIdx.x >> 6;
    __shared__ float part[4][64];
    const float* vp = V + (size_t)bh * L * D;
    float s = 0.f;
    for (int k = c * 512; k < c * 512 + 512; ++k) s += vp[(size_t)k * D + d];
    part[c][d] = s;
    __syncthreads();
    if (c == 0)
        g_vmean[bh * D + d] = (part[0][d] + part[1][d] + part[2][d] + part[3][d]) * (1.0f / 2048.0f);
}

// ---------------------------------------------------------------------------
// Main attention kernel: fp16 GEMMs, log2-domain online softmax,
// cp.async double-buffered K, V AND bias; 3 CTAs/SM (227 KB smem/SM)
// ---------------------------------------------------------------------------
__global__ __launch_bounds__(THREADS, 3)
void attn_kernel(const float* __restrict__ Q, const int* __restrict__ qmask,
                 const int* __restrict__ vmask, const float* __restrict__ bias,
                 float* __restrict__ out) {
    extern __shared__ __half smem[];
    constexpr int HT = BK * PWH;                    // halves per K/V tile
    __half* Ks[2] = { smem, smem + HT };
    __half* Vs[2] = { smem + 2 * HT, smem + 3 * HT };
    float*  Bs[2] = { (float*)(smem + 4 * HT), (float*)(smem + 4 * HT) + BQ * PB };

    const int qt = (NQT - 1) - blockIdx.x;          // big tiles first
    const int bh = blockIdx.y;
    const int q0 = qt * BQ;

    const float*  Qg = Q + ((size_t)bh * L + q0) * D;
    const __half* Kg = g_Kh + (size_t)bh * L * D;
    const __half* Vg = g_Vh + (size_t)bh * D * L;
    const float*  Bg = bias + ((size_t)bh * L + q0) * L;
    const int*   vmg = vmask + (size_t)bh * L;

    const int tid = threadIdx.x;
    const int w = tid >> 5, lane = tid & 31;
    const int g = lane >> 2, tig = lane & 3;

    const uint32_t sKs[2] = { (uint32_t)__cvta_generic_to_shared(Ks[0]),
                              (uint32_t)__cvta_generic_to_shared(Ks[1]) };
    const uint32_t sVs[2] = { (uint32_t)__cvta_generic_to_shared(Vs[0]),
                              (uint32_t)__cvta_generic_to_shared(Vs[1]) };
    const uint32_t sBs[2] = { (uint32_t)__cvta_generic_to_shared(Bs[0]),
                              (uint32_t)__cvta_generic_to_shared(Bs[1]) };

    const int nkt = qt + 1;

    // prefetch tile 0: K,V 4 chunks/thread each; bias 8 chunks/thread
    {
#pragma unroll
        for (int i = 0; i < 4; ++i) {
            int c = tid + i * 128;
            int r = c >> 3, sg = (c & 7) * 8;       // 8 halves per 16B chunk
            cp_async16(sKs[0] + (uint32_t)(r * PWH + sg) * 2, Kg + (size_t)r * 64 + sg);
            cp_async16(sVs[0] + (uint32_t)(r * PWH + sg) * 2, Vg + (size_t)r * L + sg);
        }
#pragma unroll
        for (int i = 0; i < 8; ++i) {
            int c = tid + i * 128;
            int r = c >> 4, sg = (c & 15) * 4;      // 4 floats per 16B chunk
            cp_async16(sBs[0] + (uint32_t)(r * PB + sg) * 4, Bg + (size_t)r * L + sg);
        }
        asm volatile("cp.async.commit_group;");
    }

    const int row0 = 16 * w + g;
    const int gq0 = q0 + row0, gq1 = gq0 + 8;

    // Q fragments in registers (scaled by 0.125*log2e, fp16, m16n8k16 A layout)
    uint32_t qf[4][4];
    {
        const float* qr0 = Qg + (size_t)row0 * D;
        const float* qr1 = qr0 + 8 * D;
#pragma unroll
        for (int kk = 0; kk < 4; ++kk) {
            int c0 = 16 * kk + 2 * tig;
            qf[kk][0] = packh2(qr0[c0] * SCL, qr0[c0 + 1] * SCL);
            qf[kk][1] = packh2(qr1[c0] * SCL, qr1[c0 + 1] * SCL);
            qf[kk][2] = packh2(qr0[c0 + 8] * SCL, qr0[c0 + 9] * SCL);
            qf[kk][3] = packh2(qr1[c0 + 8] * SCL, qr1[c0 + 9] * SCL);
        }
    }

    float o[8][4];
    float l0 = 0.f, l1 = 0.f, m0 = -1e30f, m1 = -1e30f;   // log2-domain
#pragma unroll
    for (int j = 0; j < 8; ++j) { o[j][0] = o[j][1] = o[j][2] = o[j][3] = 0.f; }

    for (int kt = 0; kt < nkt; ++kt) {
        const int k0 = kt * BK;
        const int buf = kt & 1;
        asm volatile("cp.async.wait_group 0;");
        __syncthreads();

        if (kt + 1 < nkt) {
            const int nk0 = (kt + 1) * BK;
            const int nb = buf ^ 1;
#pragma unroll
            for (int i = 0; i < 4; ++i) {
                int c = tid + i * 128;
                int r = c >> 3, sg = (c & 7) * 8;
                cp_async16(sKs[nb] + (uint32_t)(r * PWH + sg) * 2, Kg + (size_t)(nk0 + r) * 64 + sg);
                cp_async16(sVs[nb] + (uint32_t)(r * PWH + sg) * 2, Vg + (size_t)r * L + nk0 + sg);
            }
#pragma unroll
            for (int i = 0; i < 8; ++i) {
                int c = tid + i * 128;
                int r = c >> 4, sg = (c & 15) * 4;
                cp_async16(sBs[nb] + (uint32_t)(r * PB + sg) * 4, Bg + (size_t)r * L + nk0 + sg);
            }
            asm volatile("cp.async.commit_group;");
        }

        uint32_t mw0 = __ballot_sync(0xffffffffu, vmg[k0 + lane] != 0);
        uint32_t mw1 = __ballot_sync(0xffffffffu, vmg[k0 + 32 + lane] != 0);
        const int lim0 = gq0 - k0, lim1 = lim0 + 8;

        // ---- S = Q K^T (fp16 m16n8k16, A from regs, B one LDS.64 each) ----
        float s[8][4];
#pragma unroll
        for (int j = 0; j < 8; ++j) { s[j][0] = s[j][1] = s[j][2] = s[j][3] = 0.f; }
        const __half* Kb = Ks[buf];
#pragma unroll
        for (int kk = 0; kk < 4; ++kk) {
            int co = 16 * kk + 4 * tig;              // interleaved d pos (halves)
#pragma unroll
            for (int j = 0; j < 8; ++j) {
                uint2 b = *(const uint2*)(Kb + (8 * j + g) * PWH + co);
                mma16h(s[j], qf[kk][0], qf[kk][1], qf[kk][2], qf[kk][3], b.x, b.y);
            }
        }

        // ---- bias (smem, FFMA with log2e) + validity; tile max over valid ----
        const float* Bb0 = Bs[buf] + row0 * PB;
        const float* Bb1 = Bb0 + 8 * PB;
        bool v0[8], v1[8], v2[8], v3[8];
        float tm0 = -1e30f, tm1 = -1e30f;
#pragma unroll
        for (int j = 0; j < 8; ++j) {
            int c0 = 8 * j + 2 * tig;
            float2 bv0 = *(const float2*)(Bb0 + c0);
            float2 bv1 = *(const float2*)(Bb1 + c0);
            uint32_t mw = (c0 < 32) ? mw0 : mw1;
            bool mk0 = (mw >> (c0 & 31)) & 1u;
            bool mk1 = (mw >> ((c0 + 1) & 31)) & 1u;
            v0[j] = mk0 && (c0     <= lim0);
            v1[j] = mk1 && (c0 + 1 <= lim0);
            v2[j] = mk0 && (c0     <= lim1);
            v3[j] = mk1 && (c0 + 1 <= lim1);
            s[j][0] = fmaf(bv0.x, LOG2E, s[j][0]);
            s[j][1] = fmaf(bv0.y, LOG2E, s[j][1]);
            s[j][2] = fmaf(bv1.x, LOG2E, s[j][2]);
            s[j][3] = fmaf(bv1.y, LOG2E, s[j][3]);
            tm0 = fmaxf(tm0, fmaxf(v0[j] ? s[j][0] : -1e30f, v1[j] ? s[j][1] : -1e30f));
            tm1 = fmaxf(tm1, fmaxf(v2[j] ? s[j][2] : -1e30f, v3[j] ? s[j][3] : -1e30f));
        }
        tm0 = fmaxf(tm0, __shfl_xor_sync(0xffffffffu, tm0, 1));
        tm0 = fmaxf(tm0, __shfl_xor_sync(0xffffffffu, tm0, 2));
        tm1 = fmaxf(tm1, __shfl_xor_sync(0xffffffffu, tm1, 1));
        tm1 = fmaxf(tm1, __shfl_xor_sync(0xffffffffu, tm1, 2));
        float nm0 = fmaxf(m0, tm0), nm1 = fmaxf(m1, tm1);
        float al0 = ex2(m0 - nm0), al1 = ex2(m1 - nm1);
        m0 = nm0; m1 = nm1;

        // ---- exp2 + pack P directly into fp16 A-fragments ----
        uint32_t p[4][4];
        float a0s = 0.f, a1s = 0.f;
#pragma unroll
        for (int j = 0; j < 8; ++j) {
            float e0 = v0[j] ? ex2(s[j][0] - m0) : 0.f;
            float e1 = v1[j] ? ex2(s[j][1] - m0) : 0.f;
            float e2 = v2[j] ? ex2(s[j][2] - m1) : 0.f;
            float e3 = v3[j] ? ex2(s[j][3] - m1) : 0.f;
            a0s += e0 + e1;
            a1s += e2 + e3;
            int kk = j >> 1;
            if ((j & 1) == 0) {
                p[kk][0] = packh2(e0, e1);   // rows g,   keys 16kk+2tig..+1
                p[kk][1] = packh2(e2, e3);   // rows g+8
            } else {
                p[kk][2] = packh2(e0, e1);   // rows g,   keys 16kk+2tig+8..+9
                p[kk][3] = packh2(e2, e3);   // rows g+8
            }
        }
        l0 = l0 * al0 + a0s;
        l1 = l1 * al1 + a1s;

        // ---- rescale O, then O += P V (fp16 m16n8k16) ----
        const __half* Vb = Vs[buf];
#pragma unroll
        for (int j = 0; j < 8; ++j) {
            o[j][0] *= al0; o[j][1] *= al0; o[j][2] *= al1; o[j][3] *= al1;
        }
#pragma unroll
        for (int kk = 0; kk < 4; ++kk) {
            int co = 16 * kk + 4 * tig;              // interleaved key pos (halves)
#pragma unroll
            for (int j = 0; j < 8; ++j) {
                uint2 b = *(const uint2*)(Vb + (8 * j + g) * PWH + co);
                mma16h(o[j], p[kk][0], p[kk][1], p[kk][2], p[kk][3], b.x, b.y);
            }
        }
    }

    // ---- epilogue: deferred l reduction over the quad ----
    l0 += __shfl_xor_sync(0xffffffffu, l0, 1);
    l0 += __shfl_xor_sync(0xffffffffu, l0, 2);
    l1 += __shfl_xor_sync(0xffffffffu, l1, 1);
    l1 += __shfl_xor_sync(0xffffffffu, l1, 2);

    int qm0 = qmask[(size_t)bh * L + gq0];
    int qm1 = qmask[(size_t)bh * L + gq1];
    bool fm0 = (l0 == 0.f), fm1 = (l1 == 0.f);
    float il0 = fm0 ? 0.f : 1.0f / l0;
    float il1 = fm1 ? 0.f : 1.0f / l1;
#pragma unroll
    for (int j = 0; j < 8; ++j) {
        int c = 8 * j + 2 * tig;
        float2 r0, r1;
        r0.x = !qm0 ? 0.f : (fm0 ? g_vmean[bh * D + c]     : o[j][0] * il0);
        r0.y = !qm0 ? 0.f : (fm0 ? g_vmean[bh * D + c + 1] : o[j][1] * il0);
        r1.x = !qm1 ? 0.f : (fm1 ? g_vmean[bh * D + c]     : o[j][2] * il1);
        r1.y = !qm1 ? 0.f : (fm1 ? g_vmean[bh * D + c + 1] : o[j][3] * il1);
        *(float2*)(out + ((size_t)bh * L + gq0) * D + c) = r0;
        *(float2*)(out + ((size_t)bh * L + gq1) * D + c) = r1;
    }
}

// ---------------------------------------------------------------------------
extern "C" void kernel_launch(void* const* d_in, const int* in_sizes, int n_in,
                              void* d_out, int out_size) {
    const float* Q  = (const float*)d_in[0];
    const float* K  = (const float*)d_in[1];
    const float* V  = (const float*)d_in[2];
    const int* qm   = (const int*)d_in[3];
    const int* vm   = (const int*)d_in[4];
    const float* bi = (const float*)d_in[5];
    float* out = (float*)d_out;

    constexpr int SMEM_BYTES = 4 * BK * PWH * 2 + 2 * BQ * PB * 4;  // 40960 + 34816 = 75776
    cudaFuncSetAttribute(attn_kernel, cudaFuncAttributeMaxDynamicSharedMemorySize, SMEM_BYTES);

    kprep_kernel<<<(B * H * L * D) / 256, 256>>>(K);
    vtrans_kernel<<<dim3(L / 64, B * H), 256>>>(V);
    vmean_kernel<<<B * H, 256>>>(V);
    attn_kernel<<<dim3(NQT, B * H), THREADS, SMEM_BYTES>>>(Q, qm, vm, bi, out);
}

// round 17
// speedup vs baseline: 1.6459x; 1.1135x over previous
#include <cuda_runtime.h>
#include <cuda_fp16.h>
#include <cstdint>

constexpr int B = 2, H = 16, L = 2048, D = 64;
constexpr int BQ = 64, BK = 64;
constexpr int PWH = 80;               // K/V smem row stride (halves): 160B rows, LDS.64 conflict-free
constexpr int PB = 68;                // bias smem row stride (floats)
constexpr int THREADS = 128;
constexpr int NQT = L / BQ;           // 32
constexpr float SCL = 0.18033688011112042f;      // 0.125 * log2(e)
constexpr float LOG2E = 1.4426950408889634f;

// pre-converted fp16 operands, 16-group interleaved for m16n8k16 B-fragments
__device__ __half g_Kh[B * H * L * D];   // [bh][key][d']
__device__ __half g_Vh[B * H * D * L];   // [bh][d][key']
__device__ float  g_vmean[B * H * D];

// within-16 permutation: pos 4t..4t+3 hold elements {2t, 2t+1, 2t+8, 2t+9}
__device__ __forceinline__ int vperm16(int k) {
    int t = (k & 7) >> 1;
    return 4 * t + ((k >> 2) & 2) + (k & 1);
}

__device__ __forceinline__ void mma16h(float* c, uint32_t a0, uint32_t a1, uint32_t a2, uint32_t a3,
                                       uint32_t b0, uint32_t b1) {
    asm volatile(
        "mma.sync.aligned.m16n8k16.row.col.f32.f16.f16.f32 "
        "{%0,%1,%2,%3},{%4,%5,%6,%7},{%8,%9},{%0,%1,%2,%3};"
        : "+f"(c[0]), "+f"(c[1]), "+f"(c[2]), "+f"(c[3])
        : "r"(a0), "r"(a1), "r"(a2), "r"(a3), "r"(b0), "r"(b1));
}

__device__ __forceinline__ void cp_async16(uint32_t saddr, const void* g) {
    asm volatile("cp.async.cg.shared.global [%0], [%1], 16;" :: "r"(saddr), "l"(g));
}

__device__ __forceinline__ uint32_t packh2(float a, float b) {
    __half2 h = __floats2half2_rn(a, b);
    return *reinterpret_cast<uint32_t*>(&h);
}

__device__ __forceinline__ float ex2(float x) {
    float y; asm("ex2.approx.ftz.f32 %0, %1;" : "=f"(y) : "f"(x)); return y;
}
__device__ __forceinline__ uint32_t ex2h2(uint32_t x) {
    uint32_t y; asm("ex2.approx.f16x2 %0, %1;" : "=r"(y) : "r"(x)); return y;
}

// ---------------------------------------------------------------------------
// Pre-pass kernels
// ---------------------------------------------------------------------------
__global__ void kprep_kernel(const float* __restrict__ K) {
    int idx = blockIdx.x * 256 + threadIdx.x;
    int d = idx & 63;
    int dst = (idx & ~63) | (d & ~15) | vperm16(d & 15);
    g_Kh[dst] = __float2half_rn(K[idx]);
}

__global__ void vtrans_kernel(const float* __restrict__ V) {
    __shared__ float t[64][65];
    int k0 = blockIdx.x * 64;
    int bh = blockIdx.y;
    const float* vp = V + ((size_t)bh * L + k0) * D;
    int tid = threadIdx.x;
#pragma unroll
    for (int i = 0; i < 16; ++i) {
        int e = i * 256 + tid;
        t[e >> 6][e & 63] = vp[e];
    }
    __syncthreads();
    __half* op = g_Vh + (size_t)bh * D * L + k0;
#pragma unroll
    for (int i = 0; i < 16; ++i) {
        int e = i * 256 + tid;
        int d = e >> 6, key = e & 63;                // transpose + interleave on write
        int pos = (key & ~15) | vperm16(key & 15);
        op[(size_t)d * L + pos] = __float2half_rn(t[key][d]);
    }
}

__global__ void vmean_kernel(const float* __restrict__ V) {
    int bh = blockIdx.x;
    int d = threadIdx.x & 63;
    int c = threadIdx.x >> 6;
    __shared__ float part[4][64];
    const float* vp = V + (size_t)bh * L * D;
    float s = 0.f;
    for (int k = c * 512; k < c * 512 + 512; ++k) s += vp[(size_t)k * D + d];
    part[c][d] = s;
    __syncthreads();
    if (c == 0)
        g_vmean[bh * D + d] = (part[0][d] + part[1][d] + part[2][d] + part[3][d]) * (1.0f / 2048.0f);
}

// ---------------------------------------------------------------------------
// Main attention kernel: fp16 GEMMs, log2-domain online softmax (f16x2 exp),
// tensor-core row sums, pointer-increment cp.async pipeline; 3 CTAs/SM
// ---------------------------------------------------------------------------
__global__ __launch_bounds__(THREADS, 3)
void attn_kernel(const float* __restrict__ Q, const int* __restrict__ qmask,
                 const int* __restrict__ vmask, const float* __restrict__ bias,
                 float* __restrict__ out) {
    extern __shared__ __half smem[];
    constexpr int HT = BK * PWH;                    // halves per K/V tile (5120)
    __half* Ks[2] = { smem, smem + HT };
    __half* Vs[2] = { smem + 2 * HT, smem + 3 * HT };
    float*  Bs[2] = { (float*)(smem + 4 * HT), (float*)(smem + 4 * HT) + BQ * PB };

    const int qt = (NQT - 1) - blockIdx.x;          // big tiles first
    const int bh = blockIdx.y;
    const int q0 = qt * BQ;

    const float*  Qg = Q + ((size_t)bh * L + q0) * D;
    const float*  Bg = bias + ((size_t)bh * L + q0) * L;
    const int*   vmg = vmask + (size_t)bh * L;

    const int tid = threadIdx.x;
    const int w = tid >> 5, lane = tid & 31;
    const int g = lane >> 2, tig = lane & 3;

    // per-thread cp.async source pointers (advance by constant per tile)
    const int krow = tid >> 3;                      // 0..15
    const int ksg  = (tid & 7) * 8;                 // halves
    const int brow = tid >> 4;                      // 0..7
    const int bsg  = (tid & 15) * 4;                // floats
    const __half* kSrc = g_Kh + (size_t)bh * L * D + (size_t)krow * 64 + ksg;
    const __half* vSrc = g_Vh + (size_t)bh * D * L + (size_t)krow * L + ksg;
    const float*  bSrc = Bg + (size_t)brow * L + bsg;

    const uint32_t sb = (uint32_t)__cvta_generic_to_shared(smem);
    const uint32_t kOff = (uint32_t)(krow * PWH + ksg) * 2;
    const uint32_t bOff = (uint32_t)(brow * PB + bsg) * 4;
    const uint32_t kD[2] = { sb + kOff, sb + HT * 2 + kOff };
    const uint32_t vD[2] = { sb + 2 * HT * 2 + kOff, sb + 3 * HT * 2 + kOff };
    const uint32_t bD[2] = { sb + 4 * HT * 2 + bOff, sb + 4 * HT * 2 + BQ * PB * 4 + bOff };

    const int nkt = qt + 1;

    // prefetch tile 0
    {
#pragma unroll
        for (int i = 0; i < 4; ++i) {
            cp_async16(kD[0] + i * (16 * PWH * 2), kSrc + i * 16 * 64);
            cp_async16(vD[0] + i * (16 * PWH * 2), vSrc + (size_t)(i * 16) * L);
        }
#pragma unroll
        for (int i = 0; i < 8; ++i)
            cp_async16(bD[0] + i * (8 * PB * 4), bSrc + (size_t)(i * 8) * L);
        asm volatile("cp.async.commit_group;");
        kSrc += BK * 64; vSrc += BK; bSrc += BK;
    }

    const int row0 = 16 * w + g;
    const int gq0 = q0 + row0, gq1 = gq0 + 8;

    // Q fragments in registers (scaled by 0.125*log2e, fp16, m16n8k16 A layout)
    uint32_t qf[4][4];
    {
        const float* qr0 = Qg + (size_t)row0 * D;
        const float* qr1 = qr0 + 8 * D;
#pragma unroll
        for (int kk = 0; kk < 4; ++kk) {
            int c0 = 16 * kk + 2 * tig;
            qf[kk][0] = packh2(qr0[c0] * SCL, qr0[c0 + 1] * SCL);
            qf[kk][1] = packh2(qr1[c0] * SCL, qr1[c0 + 1] * SCL);
            qf[kk][2] = packh2(qr0[c0 + 8] * SCL, qr0[c0 + 9] * SCL);
            qf[kk][3] = packh2(qr1[c0 + 8] * SCL, qr1[c0 + 9] * SCL);
        }
    }

    float o[8][4], osum[4] = {0.f, 0.f, 0.f, 0.f};
    float m0 = -1e5f, m1 = -1e5f;                   // log2-domain running max
#pragma unroll
    for (int j = 0; j < 8; ++j) { o[j][0] = o[j][1] = o[j][2] = o[j][3] = 0.f; }

    const uint32_t ONES2 = 0x3C003C00u;             // half2(1.0, 1.0)

    for (int kt = 0; kt < nkt; ++kt) {
        const int k0 = kt * BK;
        const int buf = kt & 1;
        asm volatile("cp.async.wait_group 0;");
        __syncthreads();

        if (kt + 1 < nkt) {
            const int nb = buf ^ 1;
            const uint32_t kd = kD[nb], vd = vD[nb], bd = bD[nb];
#pragma unroll
            for (int i = 0; i < 4; ++i) {
                cp_async16(kd + i * (16 * PWH * 2), kSrc + i * 16 * 64);
                cp_async16(vd + i * (16 * PWH * 2), vSrc + (size_t)(i * 16) * L);
            }
#pragma unroll
            for (int i = 0; i < 8; ++i)
                cp_async16(bd + i * (8 * PB * 4), bSrc + (size_t)(i * 8) * L);
            asm volatile("cp.async.commit_group;");
            kSrc += BK * 64; vSrc += BK; bSrc += BK;
        }

        uint32_t mw0 = __ballot_sync(0xffffffffu, vmg[k0 + lane] != 0);
        uint32_t mw1 = __ballot_sync(0xffffffffu, vmg[k0 + 32 + lane] != 0);
        const int lim0 = gq0 - k0, lim1 = lim0 + 8;

        // ---- S = Q K^T (fp16 m16n8k16, A from regs, B one LDS.64 each) ----
        float s[8][4];
#pragma unroll
        for (int j = 0; j < 8; ++j) { s[j][0] = s[j][1] = s[j][2] = s[j][3] = 0.f; }
        const __half* Kb = Ks[buf];
#pragma unroll
        for (int kk = 0; kk < 4; ++kk) {
            int co = 16 * kk + 4 * tig;              // interleaved d pos (halves)
#pragma unroll
            for (int j = 0; j < 8; ++j) {
                uint2 b = *(const uint2*)(Kb + (8 * j + g) * PWH + co);
                mma16h(s[j], qf[kk][0], qf[kk][1], qf[kk][2], qf[kk][3], b.x, b.y);
            }
        }

        // ---- bias + mask (single select: invalid -> -1e9) + tile max ----
        const float* Bb0 = Bs[buf] + row0 * PB;
        const float* Bb1 = Bb0 + 8 * PB;
        float tm0 = -3e38f, tm1 = -3e38f;
#pragma unroll
        for (int j = 0; j < 8; ++j) {
            int c0 = 8 * j + 2 * tig;
            float2 bv0 = *(const float2*)(Bb0 + c0);
            float2 bv1 = *(const float2*)(Bb1 + c0);
            uint32_t mw = (c0 < 32) ? mw0 : mw1;
            bool mk0 = (mw >> (c0 & 31)) & 1u;
            bool mk1 = (mw >> ((c0 + 1) & 31)) & 1u;
            s[j][0] = (mk0 && c0     <= lim0) ? fmaf(bv0.x, LOG2E, s[j][0]) : -1e9f;
            s[j][1] = (mk1 && c0 + 1 <= lim0) ? fmaf(bv0.y, LOG2E, s[j][1]) : -1e9f;
            s[j][2] = (mk0 && c0     <= lim1) ? fmaf(bv1.x, LOG2E, s[j][2]) : -1e9f;
            s[j][3] = (mk1 && c0 + 1 <= lim1) ? fmaf(bv1.y, LOG2E, s[j][3]) : -1e9f;
            tm0 = fmaxf(tm0, fmaxf(s[j][0], s[j][1]));
            tm1 = fmaxf(tm1, fmaxf(s[j][2], s[j][3]));
        }
        tm0 = fmaxf(tm0, __shfl_xor_sync(0xffffffffu, tm0, 1));
        tm0 = fmaxf(tm0, __shfl_xor_sync(0xffffffffu, tm0, 2));
        tm1 = fmaxf(tm1, __shfl_xor_sync(0xffffffffu, tm1, 1));
        tm1 = fmaxf(tm1, __shfl_xor_sync(0xffffffffu, tm1, 2));
        float nm0 = fmaxf(m0, tm0), nm1 = fmaxf(m1, tm1);
        float al0 = ex2(m0 - nm0), al1 = ex2(m1 - nm1);
        m0 = nm0; m1 = nm1;

        // ---- exp2 in f16x2: pack (s-m) then one MUFU per pair; masked -> 0 ----
        uint32_t p[4][4];
#pragma unroll
        for (int j = 0; j < 8; ++j) {
            int kk = j >> 1;
            uint32_t e01 = ex2h2(packh2(s[j][0] - m0, s[j][1] - m0));
            uint32_t e23 = ex2h2(packh2(s[j][2] - m1, s[j][3] - m1));
            if ((j & 1) == 0) { p[kk][0] = e01; p[kk][1] = e23; }
            else              { p[kk][2] = e01; p[kk][3] = e23; }
        }

        // ---- rescale O and row-sum accumulators ----
#pragma unroll
        for (int j = 0; j < 8; ++j) {
            o[j][0] *= al0; o[j][1] *= al0; o[j][2] *= al1; o[j][3] *= al1;
        }
        osum[0] *= al0; osum[1] *= al0; osum[2] *= al1; osum[3] *= al1;

        // ---- O += P V; row sums via P @ ones (tensor core, no LDS) ----
        const __half* Vb = Vs[buf];
#pragma unroll
        for (int kk = 0; kk < 4; ++kk) {
            int co = 16 * kk + 4 * tig;              // interleaved key pos (halves)
            mma16h(osum, p[kk][0], p[kk][1], p[kk][2], p[kk][3], ONES2, ONES2);
#pragma unroll
            for (int j = 0; j < 8; ++j) {
                uint2 b = *(const uint2*)(Vb + (8 * j + g) * PWH + co);
                mma16h(o[j], p[kk][0], p[kk][1], p[kk][2], p[kk][3], b.x, b.y);
            }
        }
    }

    // ---- epilogue: l comes fully reduced from the sum-mma ----
    const float l0 = osum[0], l1 = osum[2];
    int qm0 = qmask[(size_t)bh * L + gq0];
    int qm1 = qmask[(size_t)bh * L + gq1];
    bool fm0 = (l0 == 0.f), fm1 = (l1 == 0.f);
    float il0 = fm0 ? 0.f : 1.0f / l0;
    float il1 = fm1 ? 0.f : 1.0f / l1;
#pragma unroll
    for (int j = 0; j < 8; ++j) {
        int c = 8 * j + 2 * tig;
        float2 r0, r1;
        r0.x = !qm0 ? 0.f : (fm0 ? g_vmean[bh * D + c]     : o[j][0] * il0);
        r0.y = !qm0 ? 0.f : (fm0 ? g_vmean[bh * D + c + 1] : o[j][1] * il0);
        r1.x = !qm1 ? 0.f : (fm1 ? g_vmean[bh * D + c]     : o[j][2] * il1);
        r1.y = !qm1 ? 0.f : (fm1 ? g_vmean[bh * D + c + 1] : o[j][3] * il1);
        *(float2*)(out + ((size_t)bh * L + gq0) * D + c) = r0;
        *(float2*)(out + ((size_t)bh * L + gq1) * D + c) = r1;
    }
}

// ---------------------------------------------------------------------------
extern "C" void kernel_launch(void* const* d_in, const int* in_sizes, int n_in,
                              void* d_out, int out_size) {
    const float* Q  = (const float*)d_in[0];
    const float* K  = (const float*)d_in[1];
    const float* V  = (const float*)d_in[2];
    const int* qm   = (const int*)d_in[3];
    const int* vm   = (const int*)d_in[4];
    const float* bi = (const float*)d_in[5];
    float* out = (float*)d_out;

    constexpr int SMEM_BYTES = 4 * BK * PWH * 2 + 2 * BQ * PB * 4;  // 40960 + 34816 = 75776
    cudaFuncSetAttribute(attn_kernel, cudaFuncAttributeMaxDynamicSharedMemorySize, SMEM_BYTES);

    kprep_kernel<<<(B * H * L * D) / 256, 256>>>(K);
    vtrans_kernel<<<dim3(L / 64, B * H), 256>>>(V);
    vmean_kernel<<<B * H, 256>>>(V);
    attn_kernel<<<dim3(NQT, B * H), THREADS, SMEM_BYTES>>>(Q, qm, vm, bi, out);
}